// round 1
// baseline (speedup 1.0000x reference)
#include <cuda_runtime.h>
#include <cstdint>

#define ROWS 4096
#define COLS 11008
#define G    128
#define NB   86          // COLS / G

__device__ __forceinline__ float sigmoidf_(float v) {
    return 1.0f / (1.0f + expf(-v));
}

__global__ __launch_bounds__(256)
void mixq_kernel(const float* __restrict__ x,
                 const float* __restrict__ up,
                 const float* __restrict__ low,
                 float* __restrict__ out)
{
    const float CLIPMIN = 1e-5f;
    const float CLIPMAX = 10000.0f;

    // one warp per group of 128 contiguous floats
    int gw   = (blockIdx.x * blockDim.x + threadIdx.x) >> 5;
    int lane = threadIdx.x & 31;
    if (gw >= ROWS * NB) return;

    int row = gw / NB;
    int j   = gw - row * NB;

    const float4* xg = reinterpret_cast<const float4*>(x + (size_t)row * COLS + (size_t)j * G);
    float4 v = xg[lane];

    // per-lane partials
    float mn = fminf(fminf(v.x, v.y), fminf(v.z, v.w));
    float mx = fmaxf(fmaxf(v.x, v.y), fmaxf(v.z, v.w));
    float sm = (v.x + v.y) + (v.z + v.w);
    float as = (fabsf(v.x) + fabsf(v.y)) + (fabsf(v.z) + fabsf(v.w));

    // warp butterfly reduction
    #pragma unroll
    for (int o = 16; o > 0; o >>= 1) {
        mn = fminf(mn, __shfl_xor_sync(0xffffffffu, mn, o));
        mx = fmaxf(mx, __shfl_xor_sync(0xffffffffu, mx, o));
        sm += __shfl_xor_sync(0xffffffffu, sm, o);
        as += __shfl_xor_sync(0xffffffffu, as, o);
    }

    // precision of this block: _PREC = [1] + [2,3,4,3,2]*17
    int prec;
    if (j == 0) {
        prec = 1;
    } else {
        int r = (j - 1) % 5;                    // 0..4 -> 2,3,4,3,2
        prec = (r == 0) ? 2 : (r == 1) ? 3 : (r == 2) ? 4 : (r == 3) ? 3 : 2;
    }
    bool  is_t   = (prec == 1);
    float levels = (float)((1 << prec) - 1);

    float su = sigmoidf_(up[gw]);
    float sl = sigmoidf_(low[gw]);

    float mean  = sm * (1.0f / (float)G);
    float amean = as * (1.0f / (float)G);
    float xmax  = su * mx;
    float xmin  = sl * mn;

    float s, z, qmin;
    if (is_t) {
        s = fminf(fmaxf(amean * (su + 0.5f), CLIPMIN), CLIPMAX);
        z = fminf(fmaxf(mean, -CLIPMAX), CLIPMAX);   // not rounded for ternary
        qmin = -1.0f;
    } else {
        float scale_r = (xmax - xmin) / levels;
        s = fminf(fmaxf(scale_r, CLIPMIN), CLIPMAX);
        float zp = -xmin / scale_r;                  // uses UNclipped scale_r (matches ref)
        z = rintf(fminf(fmaxf(zp, -CLIPMAX), CLIPMAX));
        qmin = 0.0f;
    }

    float4 o;
    if (is_t) {
        // deq = s * clip(sign((x - z)/s), -1, 1); s > 0 so sign is in {-1,0,1}
        float tx = (v.x - z) / s;
        float ty = (v.y - z) / s;
        float tz = (v.z - z) / s;
        float tw = (v.w - z) / s;
        o.x = s * ((tx > 0.f) ? 1.f : (tx < 0.f) ? -1.f : 0.f);
        o.y = s * ((ty > 0.f) ? 1.f : (ty < 0.f) ? -1.f : 0.f);
        o.z = s * ((tz > 0.f) ? 1.f : (tz < 0.f) ? -1.f : 0.f);
        o.w = s * ((tw > 0.f) ? 1.f : (tw < 0.f) ? -1.f : 0.f);
    } else {
        float inv_s = 1.0f / s;   // exact divide once per group
        float qx = fminf(fmaxf(rintf(v.x * inv_s) + z, qmin), levels);
        float qy = fminf(fmaxf(rintf(v.y * inv_s) + z, qmin), levels);
        float qz = fminf(fmaxf(rintf(v.z * inv_s) + z, qmin), levels);
        float qw = fminf(fmaxf(rintf(v.w * inv_s) + z, qmin), levels);
        o.x = (qx - z) * s;
        o.y = (qy - z) * s;
        o.z = (qz - z) * s;
        o.w = (qw - z) * s;
    }

    float4* og = reinterpret_cast<float4*>(out + (size_t)row * COLS + (size_t)j * G);
    og[lane] = o;
}

extern "C" void kernel_launch(void* const* d_in, const int* in_sizes, int n_in,
                              void* d_out, int out_size)
{
    const float* x   = (const float*)d_in[0];
    const float* up  = (const float*)d_in[1];
    const float* low = (const float*)d_in[2];
    float* out = (float*)d_out;

    int total_warps  = ROWS * NB;             // 352256 groups, 1 warp each
    int threads      = 256;                   // 8 warps / block
    int blocks       = (total_warps * 32 + threads - 1) / threads;  // 44032

    mixq_kernel<<<blocks, threads>>>(x, up, low, out);
}

// round 2
// speedup vs baseline: 1.7116x; 1.7116x over previous
#include <cuda_runtime.h>
#include <cstdint>

#define ROWS 4096
#define COLS 11008
#define G    128
#define NB   86                      // COLS / G
#define NGROUPS (ROWS * NB)          // 352256, divisible by 4

__global__ __launch_bounds__(256)
void mixq_kernel(const float4* __restrict__ x4,
                 const float* __restrict__ up,
                 const float* __restrict__ low,
                 float4* __restrict__ out4)
{
    const float CLIPMIN = 1e-5f;
    const float CLIPMAX = 10000.0f;

    int warp = (blockIdx.x * blockDim.x + threadIdx.x) >> 5;
    int lane = threadIdx.x & 31;
    int seg  = lane >> 3;            // 0..3 : which of 4 groups this lane serves
    int off  = lane & 7;             // 0..7 : position within 8-lane segment

    int g = warp * 4 + seg;          // global group id (groups are contiguous 512B chunks)
    if (g >= NGROUPS) return;

    // group g occupies float4 indices [g*32, g*32+32)
    const float4* gp = x4 + (size_t)g * 32 + off;
    float4 a0 = gp[0];
    float4 a1 = gp[8];
    float4 a2 = gp[16];
    float4 a3 = gp[24];

    // ---- per-lane partials over 16 values ----
    float mn, mx, sm, as;
    {
        float4 m;
        m.x = fminf(fminf(a0.x, a1.x), fminf(a2.x, a3.x));
        m.y = fminf(fminf(a0.y, a1.y), fminf(a2.y, a3.y));
        m.z = fminf(fminf(a0.z, a1.z), fminf(a2.z, a3.z));
        m.w = fminf(fminf(a0.w, a1.w), fminf(a2.w, a3.w));
        mn = fminf(fminf(m.x, m.y), fminf(m.z, m.w));

        m.x = fmaxf(fmaxf(a0.x, a1.x), fmaxf(a2.x, a3.x));
        m.y = fmaxf(fmaxf(a0.y, a1.y), fmaxf(a2.y, a3.y));
        m.z = fmaxf(fmaxf(a0.z, a1.z), fmaxf(a2.z, a3.z));
        m.w = fmaxf(fmaxf(a0.w, a1.w), fmaxf(a2.w, a3.w));
        mx = fmaxf(fmaxf(m.x, m.y), fmaxf(m.z, m.w));

        m.x = (a0.x + a1.x) + (a2.x + a3.x);
        m.y = (a0.y + a1.y) + (a2.y + a3.y);
        m.z = (a0.z + a1.z) + (a2.z + a3.z);
        m.w = (a0.w + a1.w) + (a2.w + a3.w);
        sm = (m.x + m.y) + (m.z + m.w);

        m.x = (fabsf(a0.x) + fabsf(a1.x)) + (fabsf(a2.x) + fabsf(a3.x));
        m.y = (fabsf(a0.y) + fabsf(a1.y)) + (fabsf(a2.y) + fabsf(a3.y));
        m.z = (fabsf(a0.z) + fabsf(a1.z)) + (fabsf(a2.z) + fabsf(a3.z));
        m.w = (fabsf(a0.w) + fabsf(a1.w)) + (fabsf(a2.w) + fabsf(a3.w));
        as = (m.x + m.y) + (m.z + m.w);
    }

    // ---- segmented butterfly: offsets 1,2,4 stay inside each 8-lane segment ----
    #pragma unroll
    for (int o = 1; o < 8; o <<= 1) {
        mn = fminf(mn, __shfl_xor_sync(0xffffffffu, mn, o));
        mx = fmaxf(mx, __shfl_xor_sync(0xffffffffu, mx, o));
        sm += __shfl_xor_sync(0xffffffffu, sm, o);
        as += __shfl_xor_sync(0xffffffffu, as, o);
    }

    // ---- per-group parameters (redundant across the 8 lanes of a segment) ----
    int j = g % NB;                  // block index within the row
    bool is_t = (j == 0);
    int prec;
    if (is_t) {
        prec = 1;
    } else {
        int r = (j - 1) % 5;         // pattern 2,3,4,3,2
        prec = (r == 0) ? 2 : (r == 1) ? 3 : (r == 2) ? 4 : (r == 3) ? 3 : 2;
    }
    float levels = (float)((1 << prec) - 1);

    float su = 1.0f / (1.0f + __expf(-up[g]));
    float sl = 1.0f / (1.0f + __expf(-low[g]));

    float mean  = sm * (1.0f / (float)G);
    float amean = as * (1.0f / (float)G);
    float xmax  = su * mx;
    float xmin  = sl * mn;

    float4 o0, o1, o2, o3;
    if (is_t) {
        float s = fminf(fmaxf(amean * (su + 0.5f), CLIPMIN), CLIPMAX);
        float z = fminf(fmaxf(mean, -CLIPMAX), CLIPMAX);
        float ns = -s;
        // deq = s * sign(x - z)   (s > 0)
        o0.x = (a0.x > z) ? s : (a0.x < z) ? ns : 0.0f;
        o0.y = (a0.y > z) ? s : (a0.y < z) ? ns : 0.0f;
        o0.z = (a0.z > z) ? s : (a0.z < z) ? ns : 0.0f;
        o0.w = (a0.w > z) ? s : (a0.w < z) ? ns : 0.0f;
        o1.x = (a1.x > z) ? s : (a1.x < z) ? ns : 0.0f;
        o1.y = (a1.y > z) ? s : (a1.y < z) ? ns : 0.0f;
        o1.z = (a1.z > z) ? s : (a1.z < z) ? ns : 0.0f;
        o1.w = (a1.w > z) ? s : (a1.w < z) ? ns : 0.0f;
        o2.x = (a2.x > z) ? s : (a2.x < z) ? ns : 0.0f;
        o2.y = (a2.y > z) ? s : (a2.y < z) ? ns : 0.0f;
        o2.z = (a2.z > z) ? s : (a2.z < z) ? ns : 0.0f;
        o2.w = (a2.w > z) ? s : (a2.w < z) ? ns : 0.0f;
        o3.x = (a3.x > z) ? s : (a3.x < z) ? ns : 0.0f;
        o3.y = (a3.y > z) ? s : (a3.y < z) ? ns : 0.0f;
        o3.z = (a3.z > z) ? s : (a3.z < z) ? ns : 0.0f;
        o3.w = (a3.w > z) ? s : (a3.w < z) ? ns : 0.0f;
    } else {
        float scale_r = (xmax - xmin) / levels;
        float s  = fminf(fmaxf(scale_r, CLIPMIN), CLIPMAX);
        float zp = -xmin / scale_r;                        // unclipped scale_r (matches ref)
        float z  = rintf(fminf(fmaxf(zp, -CLIPMAX), CLIPMAX));
        float inv_s = 1.0f / s;
        float qlo = 0.0f   - z;                            // qmin - z (exact: integers)
        float qhi = levels - z;                            // qmax - z (exact: integers)
        // deq = clamp(rint(x*inv_s), qlo, qhi) * s
        o0.x = fminf(fmaxf(rintf(a0.x * inv_s), qlo), qhi) * s;
        o0.y = fminf(fmaxf(rintf(a0.y * inv_s), qlo), qhi) * s;
        o0.z = fminf(fmaxf(rintf(a0.z * inv_s), qlo), qhi) * s;
        o0.w = fminf(fmaxf(rintf(a0.w * inv_s), qlo), qhi) * s;
        o1.x = fminf(fmaxf(rintf(a1.x * inv_s), qlo), qhi) * s;
        o1.y = fminf(fmaxf(rintf(a1.y * inv_s), qlo), qhi) * s;
        o1.z = fminf(fmaxf(rintf(a1.z * inv_s), qlo), qhi) * s;
        o1.w = fminf(fmaxf(rintf(a1.w * inv_s), qlo), qhi) * s;
        o2.x = fminf(fmaxf(rintf(a2.x * inv_s), qlo), qhi) * s;
        o2.y = fminf(fmaxf(rintf(a2.y * inv_s), qlo), qhi) * s;
        o2.z = fminf(fmaxf(rintf(a2.z * inv_s), qlo), qhi) * s;
        o2.w = fminf(fmaxf(rintf(a2.w * inv_s), qlo), qhi) * s;
        o3.x = fminf(fmaxf(rintf(a3.x * inv_s), qlo), qhi) * s;
        o3.y = fminf(fmaxf(rintf(a3.y * inv_s), qlo), qhi) * s;
        o3.z = fminf(fmaxf(rintf(a3.z * inv_s), qlo), qhi) * s;
        o3.w = fminf(fmaxf(rintf(a3.w * inv_s), qlo), qhi) * s;
    }

    float4* op = out4 + (size_t)g * 32 + off;
    op[0]  = o0;
    op[8]  = o1;
    op[16] = o2;
    op[24] = o3;
}

extern "C" void kernel_launch(void* const* d_in, const int* in_sizes, int n_in,
                              void* d_out, int out_size)
{
    const float4* x4  = (const float4*)d_in[0];
    const float*  up  = (const float*)d_in[1];
    const float*  low = (const float*)d_in[2];
    float4* out4 = (float4*)d_out;

    int warps   = NGROUPS / 4;                 // 88064
    int threads = 256;                         // 8 warps / block
    int blocks  = (warps * 32) / threads;      // 11008

    mixq_kernel<<<blocks, threads>>>(x4, up, low, out4);
}

// round 3
// speedup vs baseline: 1.8106x; 1.0578x over previous
#include <cuda_runtime.h>
#include <cstdint>

#define ROWS 4096
#define COLS 11008
#define G    128
#define NB   86                      // COLS / G
#define NGROUPS (ROWS * NB)          // 352256, divisible by 4

__global__ __launch_bounds__(256, 8)
void mixq_kernel(const float4* __restrict__ x4,
                 const float* __restrict__ up,
                 const float* __restrict__ low,
                 float4* __restrict__ out4)
{
    const float CLIPMIN = 1e-5f;
    const float CLIPMAX = 10000.0f;

    int warp = (blockIdx.x * blockDim.x + threadIdx.x) >> 5;
    int lane = threadIdx.x & 31;
    int seg  = lane >> 3;            // which of 4 groups this lane serves
    int off  = lane & 7;             // position within 8-lane segment

    int g = warp * 4 + seg;          // global group id
    if (g >= NGROUPS) return;

    // group g occupies float4 indices [g*32, g*32+32)
    const float4* gp = x4 + (size_t)g * 32 + off;
    float4 a0 = __ldcs(gp);
    float4 a1 = __ldcs(gp + 8);
    float4 a2 = __ldcs(gp + 16);
    float4 a3 = __ldcs(gp + 24);

    // ---- per-lane partials over 16 values ----
    float mn, mx, sm, as;
    {
        float t0, t1, t2, t3;
        t0 = fminf(fminf(a0.x, a1.x), fminf(a2.x, a3.x));
        t1 = fminf(fminf(a0.y, a1.y), fminf(a2.y, a3.y));
        t2 = fminf(fminf(a0.z, a1.z), fminf(a2.z, a3.z));
        t3 = fminf(fminf(a0.w, a1.w), fminf(a2.w, a3.w));
        mn = fminf(fminf(t0, t1), fminf(t2, t3));

        t0 = fmaxf(fmaxf(a0.x, a1.x), fmaxf(a2.x, a3.x));
        t1 = fmaxf(fmaxf(a0.y, a1.y), fmaxf(a2.y, a3.y));
        t2 = fmaxf(fmaxf(a0.z, a1.z), fmaxf(a2.z, a3.z));
        t3 = fmaxf(fmaxf(a0.w, a1.w), fmaxf(a2.w, a3.w));
        mx = fmaxf(fmaxf(t0, t1), fmaxf(t2, t3));

        t0 = (a0.x + a1.x) + (a2.x + a3.x);
        t1 = (a0.y + a1.y) + (a2.y + a3.y);
        t2 = (a0.z + a1.z) + (a2.z + a3.z);
        t3 = (a0.w + a1.w) + (a2.w + a3.w);
        sm = (t0 + t1) + (t2 + t3);

        t0 = (fabsf(a0.x) + fabsf(a1.x)) + (fabsf(a2.x) + fabsf(a3.x));
        t1 = (fabsf(a0.y) + fabsf(a1.y)) + (fabsf(a2.y) + fabsf(a3.y));
        t2 = (fabsf(a0.z) + fabsf(a1.z)) + (fabsf(a2.z) + fabsf(a3.z));
        t3 = (fabsf(a0.w) + fabsf(a1.w)) + (fabsf(a2.w) + fabsf(a3.w));
        as = (t0 + t1) + (t2 + t3);
    }

    // ---- segmented butterfly: offsets 1,2,4 stay inside each 8-lane segment ----
    #pragma unroll
    for (int o = 1; o < 8; o <<= 1) {
        mn = fminf(mn, __shfl_xor_sync(0xffffffffu, mn, o));
        mx = fmaxf(mx, __shfl_xor_sync(0xffffffffu, mx, o));
        sm += __shfl_xor_sync(0xffffffffu, sm, o);
        as += __shfl_xor_sync(0xffffffffu, as, o);
    }

    // ---- per-group parameters ----
    int j = g % NB;                  // block index within the row
    bool is_t = (j == 0);
    int prec;
    if (is_t) {
        prec = 1;
    } else {
        int r = (j - 1) % 5;         // pattern 2,3,4,3,2
        prec = (r == 0) ? 2 : (r == 1) ? 3 : (r == 2) ? 4 : (r == 3) ? 3 : 2;
    }
    float levels = (float)((1 << prec) - 1);

    float su = 1.0f / (1.0f + __expf(-__ldg(up + g)));
    float sl = 1.0f / (1.0f + __expf(-__ldg(low + g)));

    float mean  = sm * (1.0f / (float)G);
    float amean = as * (1.0f / (float)G);
    float xmax  = su * mx;
    float xmin  = sl * mn;

    if (is_t) {
        float s = fminf(fmaxf(amean * (su + 0.5f), CLIPMIN), CLIPMAX);
        float z = fminf(fmaxf(mean, -CLIPMAX), CLIPMAX);
        float ns = -s;
        // deq = s * sign(x - z)   (s > 0), written in place
        a0.x = (a0.x > z) ? s : (a0.x < z) ? ns : 0.0f;
        a0.y = (a0.y > z) ? s : (a0.y < z) ? ns : 0.0f;
        a0.z = (a0.z > z) ? s : (a0.z < z) ? ns : 0.0f;
        a0.w = (a0.w > z) ? s : (a0.w < z) ? ns : 0.0f;
        a1.x = (a1.x > z) ? s : (a1.x < z) ? ns : 0.0f;
        a1.y = (a1.y > z) ? s : (a1.y < z) ? ns : 0.0f;
        a1.z = (a1.z > z) ? s : (a1.z < z) ? ns : 0.0f;
        a1.w = (a1.w > z) ? s : (a1.w < z) ? ns : 0.0f;
        a2.x = (a2.x > z) ? s : (a2.x < z) ? ns : 0.0f;
        a2.y = (a2.y > z) ? s : (a2.y < z) ? ns : 0.0f;
        a2.z = (a2.z > z) ? s : (a2.z < z) ? ns : 0.0f;
        a2.w = (a2.w > z) ? s : (a2.w < z) ? ns : 0.0f;
        a3.x = (a3.x > z) ? s : (a3.x < z) ? ns : 0.0f;
        a3.y = (a3.y > z) ? s : (a3.y < z) ? ns : 0.0f;
        a3.z = (a3.z > z) ? s : (a3.z < z) ? ns : 0.0f;
        a3.w = (a3.w > z) ? s : (a3.w < z) ? ns : 0.0f;
    } else {
        float scale_r = (xmax - xmin) / levels;
        float s  = fminf(fmaxf(scale_r, CLIPMIN), CLIPMAX);
        float zp = -xmin / scale_r;                        // unclipped scale_r (matches ref)
        float z  = rintf(fminf(fmaxf(zp, -CLIPMAX), CLIPMAX));
        float inv_s = 1.0f / s;
        float qlo = 0.0f   - z;                            // qmin - z (exact: integers)
        float qhi = levels - z;                            // qmax - z (exact: integers)
        // deq = clamp(rint(x*inv_s), qlo, qhi) * s, written in place
        a0.x = fminf(fmaxf(rintf(a0.x * inv_s), qlo), qhi) * s;
        a0.y = fminf(fmaxf(rintf(a0.y * inv_s), qlo), qhi) * s;
        a0.z = fminf(fmaxf(rintf(a0.z * inv_s), qlo), qhi) * s;
        a0.w = fminf(fmaxf(rintf(a0.w * inv_s), qlo), qhi) * s;
        a1.x = fminf(fmaxf(rintf(a1.x * inv_s), qlo), qhi) * s;
        a1.y = fminf(fmaxf(rintf(a1.y * inv_s), qlo), qhi) * s;
        a1.z = fminf(fmaxf(rintf(a1.z * inv_s), qlo), qhi) * s;
        a1.w = fminf(fmaxf(rintf(a1.w * inv_s), qlo), qhi) * s;
        a2.x = fminf(fmaxf(rintf(a2.x * inv_s), qlo), qhi) * s;
        a2.y = fminf(fmaxf(rintf(a2.y * inv_s), qlo), qhi) * s;
        a2.z = fminf(fmaxf(rintf(a2.z * inv_s), qlo), qhi) * s;
        a2.w = fminf(fmaxf(rintf(a2.w * inv_s), qlo), qhi) * s;
        a3.x = fminf(fmaxf(rintf(a3.x * inv_s), qlo), qhi) * s;
        a3.y = fminf(fmaxf(rintf(a3.y * inv_s), qlo), qhi) * s;
        a3.z = fminf(fmaxf(rintf(a3.z * inv_s), qlo), qhi) * s;
        a3.w = fminf(fmaxf(rintf(a3.w * inv_s), qlo), qhi) * s;
    }

    float4* op = out4 + (size_t)g * 32 + off;
    __stcs(op,      a0);
    __stcs(op + 8,  a1);
    __stcs(op + 16, a2);
    __stcs(op + 24, a3);
}

extern "C" void kernel_launch(void* const* d_in, const int* in_sizes, int n_in,
                              void* d_out, int out_size)
{
    const float4* x4  = (const float4*)d_in[0];
    const float*  up  = (const float*)d_in[1];
    const float*  low = (const float*)d_in[2];
    float4* out4 = (float4*)d_out;

    int warps   = NGROUPS / 4;                 // 88064
    int threads = 256;                         // 8 warps / block
    int blocks  = (warps * 32) / threads;      // 11008

    mixq_kernel<<<blocks, threads>>>(x4, up, low, out4);
}